// round 4
// baseline (speedup 1.0000x reference)
#include <cuda_runtime.h>
#include <math.h>

#define Bq   8
#define Nq   1024
#define Hq   200
#define BNr  (Bq*Nq)
#define NCH  8

// ---------------- scratch (no allocs allowed) ----------------
__device__ float g_outs  [BNr*Hq];
__device__ float g_output[BNr*Hq];
__device__ float g_bufA  [BNr*Hq];
__device__ float g_bufB  [BNr*Hq];
__device__ float g_bufC  [BNr*Hq];
__device__ float g_scores[Bq*Nq*Nq];
__device__ float g_denom [BNr];
__device__ float g_rmax  [BNr];
__device__ float g_rsum  [BNr];
__device__ float g_cmax  [BNr];
__device__ float g_csum  [BNr];
__device__ float g_pmax  [NCH*BNr];
__device__ float g_psum  [NCH*BNr];

// ---------------- helpers ----------------
__device__ __forceinline__ float warp_red_sum(float v){
#pragma unroll
    for (int o=16;o;o>>=1) v += __shfl_xor_sync(0xffffffffu, v, o);
    return v;
}
__device__ __forceinline__ float warp_red_max(float v){
#pragma unroll
    for (int o=16;o;o>>=1) v = fmaxf(v, __shfl_xor_sync(0xffffffffu, v, o));
    return v;
}

// ---------------- unified tiled GEMM ----------------
// C[b,i,j] = epi( sum_k Aelem(b,i,k) * Belem(b,k,j) )
// AM: 0 plain row-major A[b,i,k]; 1 expf(A[b,i,k]-stat1[b*M+i]); 2 expf(A[b,k,i]-stat1[b*M+i]) (transposed)
// BM: 0 row-major B[b,k,j]; 1 transposed B[b,j,k]
// EPI: 0 +bias(opt); 1 +bias+res; 2 gelu(+bias); 3 *scale+keymask; 4 +pairmask;
//      5 relu(acc/stat1[b,i])+res; 6 acc/stat2[b,i]*tm[b,i]+res
template<int AM,int BM,int EPI>
__global__ void __launch_bounds__(256)
gemm_k(const float* __restrict__ A, const float* __restrict__ Bm, float* __restrict__ C,
       int M, int Nc, int Kd, int lda, int ldb, int ldc,
       long sA_, long sB_, long sC_,
       const float* __restrict__ bias, const float* __restrict__ res,
       const float* __restrict__ st1,  const float* __restrict__ st2,
       const float* __restrict__ tm, float scale)
{
    __shared__ float shA[64][17];
    __shared__ float shB[16][65];
    const int b  = blockIdx.z;
    const int i0 = blockIdx.y*64, j0 = blockIdx.x*64;
    const int tid = threadIdx.x;
    const int tx = tid & 15, ty = tid >> 4;
    const float* Ab = A + (long)b*sA_;
    const float* Bb = Bm + (long)b*sB_;

    float acc[4][4];
#pragma unroll
    for (int ii=0;ii<4;ii++)
#pragma unroll
        for (int jj=0;jj<4;jj++) acc[ii][jj]=0.f;

    for (int k0=0;k0<Kd;k0+=16){
        // ---- load A tile 64x16 ----
        if (AM==2){
#pragma unroll
            for (int l=0;l<4;l++){
                int idx=l*256+tid; int kk=idx>>6, row=idx&63;
                int gi=i0+row, gk=k0+kk;
                float v=0.f;
                if (gi<M && gk<Kd) v = __expf(Ab[(long)gk*lda+gi] - st1[b*M+gi]);
                shA[row][kk]=v;
            }
        } else {
#pragma unroll
            for (int l=0;l<4;l++){
                int idx=l*256+tid; int row=idx>>4, kk=idx&15;
                int gi=i0+row, gk=k0+kk;
                float v=0.f;
                if (gi<M && gk<Kd){
                    v = Ab[(long)gi*lda+gk];
                    if (AM==1) v = __expf(v - st1[b*M+gi]);
                }
                shA[row][kk]=v;
            }
        }
        // ---- load B tile 16x64 ----
        if (BM==0){
#pragma unroll
            for (int l=0;l<4;l++){
                int idx=l*256+tid; int kk=idx>>6, col=idx&63;
                int gk=k0+kk, gj=j0+col;
                shB[kk][col] = (gk<Kd && gj<Nc) ? Bb[(long)gk*ldb+gj] : 0.f;
            }
        } else {
#pragma unroll
            for (int l=0;l<4;l++){
                int idx=l*256+tid; int col=idx>>4, kk=idx&15;
                int gk=k0+kk, gj=j0+col;
                shB[kk][col] = (gk<Kd && gj<Nc) ? Bb[(long)gj*ldb+gk] : 0.f;
            }
        }
        __syncthreads();
#pragma unroll
        for (int kk=0;kk<16;kk++){
            float a[4], bb[4];
#pragma unroll
            for (int ii=0;ii<4;ii++) a[ii]=shA[ty*4+ii][kk];
#pragma unroll
            for (int jj=0;jj<4;jj++) bb[jj]=shB[kk][tx*4+jj];
#pragma unroll
            for (int ii=0;ii<4;ii++)
#pragma unroll
                for (int jj=0;jj<4;jj++)
                    acc[ii][jj] = fmaf(a[ii], bb[jj], acc[ii][jj]);
        }
        __syncthreads();
    }
    // ---- epilogue ----
#pragma unroll
    for (int ii=0;ii<4;ii++){
        int gi=i0+ty*4+ii;
        if (gi>=M) continue;
#pragma unroll
        for (int jj=0;jj<4;jj++){
            int gj=j0+tx*4+jj;
            if (gj>=Nc) continue;
            float v = acc[ii][jj];
            long cidx = (long)b*sC_ + (long)gi*ldc + gj;
            if (EPI==0){ if (bias) v += bias[gj]; }
            else if (EPI==1){ v += bias[gj]; v += res[cidx]; }
            else if (EPI==2){ v += bias[gj]; v = 0.5f*v*(1.f+erff(v*0.70710678f)); }
            else if (EPI==3){ v = v*scale + (tm[b*Nq+gj]-1.f)*10000.f; }
            else if (EPI==4){ v = v + (tm[b*Nq+gi]*tm[b*Nq+gj]-1.f)*10000.f; }
            else if (EPI==5){ v = fmaxf(v/st1[b*M+gi], 0.f) + res[cidx]; }
            else if (EPI==6){ v = v/st2[b*M+gi]*tm[b*Nq+gi] + res[cidx]; }
            C[cidx] = v;
        }
    }
}

// ---------------- softmax / stats ----------------
template<bool WRITE>
__global__ void __launch_bounds__(256)
softmax_row_k(float* __restrict__ S, float* __restrict__ rmax, float* __restrict__ rsum){
    long row = blockIdx.x;
    float* p = S + row*(long)Nq;
    int t = threadIdx.x;
    float v[4];
    float mx = -1e30f;
#pragma unroll
    for (int l=0;l<4;l++){ v[l]=p[t+l*256]; mx=fmaxf(mx,v[l]); }
    __shared__ float sm[8];
    mx = warp_red_max(mx);
    if ((t&31)==0) sm[t>>5]=mx;
    __syncthreads();
    float m2 = sm[0];
#pragma unroll
    for (int w=1;w<8;w++) m2 = fmaxf(m2, sm[w]);
    float s = 0.f;
#pragma unroll
    for (int l=0;l<4;l++){ v[l]=__expf(v[l]-m2); s+=v[l]; }
    __syncthreads();
    s = warp_red_sum(s);
    if ((t&31)==0) sm[t>>5]=s;
    __syncthreads();
    float st = 0.f;
#pragma unroll
    for (int w=0;w<8;w++) st += sm[w];
    if (WRITE){
        float inv = 1.f/st;
#pragma unroll
        for (int l=0;l<4;l++) p[t+l*256] = v[l]*inv;
    } else if (t==0){ rmax[row]=m2; rsum[row]=st; }
}

__global__ void __launch_bounds__(256)
colstats_part(const float* __restrict__ L, float* __restrict__ pmax, float* __restrict__ psum){
    int g  = blockIdx.x*256 + threadIdx.x;       // 0..BNr-1 : (b,m)
    int ch = blockIdx.y;
    int b = g >> 10, m = g & 1023;
    const float* p = L + (long)b*Nq*Nq + m + (long)ch*(Nq/NCH)*Nq;
    float mx=-1e30f, s=0.f;
#pragma unroll 4
    for (int n=0;n<Nq/NCH;n++){
        float x = p[(long)n*Nq];
        if (x>mx){ s = s*__expf(mx-x) + 1.f; mx = x; }
        else       s += __expf(x-mx);
    }
    pmax[ch*BNr+g]=mx; psum[ch*BNr+g]=s;
}
__global__ void __launch_bounds__(256)
colstats_comb(const float* __restrict__ pmax, const float* __restrict__ psum,
              float* __restrict__ cmax, float* __restrict__ csum){
    int g = blockIdx.x*256 + threadIdx.x;
    float mx=-1e30f, s=0.f;
#pragma unroll
    for (int ch=0; ch<NCH; ch++){
        float m2=pmax[ch*BNr+g], s2=psum[ch*BNr+g];
        if (m2>mx){ s = s*__expf(mx-m2) + s2; mx = m2; }
        else        s += s2*__expf(m2-mx);
    }
    cmax[g]=mx; csum[g]=s;
}

// ---------------- layernorm (1 warp / row, H=200) ----------------
__global__ void __launch_bounds__(32)
ln_k(const float* __restrict__ X, const float* __restrict__ g,
     const float* __restrict__ bt, float* __restrict__ Y){
    long row = blockIdx.x;
    const float* x = X + row*Hq;
    float* y = Y + row*Hq;
    int t = threadIdx.x;
    float v[7]; float s=0.f;
#pragma unroll
    for (int l=0;l<7;l++){ int c=t+l*32; v[l]=(c<Hq)?x[c]:0.f; s+=v[l]; }
    s = warp_red_sum(s);
    float mu = s*(1.f/Hq);
    float var = 0.f;
#pragma unroll
    for (int l=0;l<7;l++){ int c=t+l*32; if (c<Hq){ float d=v[l]-mu; var+=d*d; } }
    var = warp_red_sum(var)*(1.f/Hq);
    float r = rsqrtf(var + 1e-20f);
#pragma unroll
    for (int l=0;l<7;l++){ int c=t+l*32; if (c<Hq) y[c] = (v[l]-mu)*r*g[c]+bt[c]; }
}

// ---------------- adj + denom ----------------
__global__ void __launch_bounds__(256)
adj_k(const float* __restrict__ a1, const float* __restrict__ a2,
      float* __restrict__ adjo, float* __restrict__ den){
    long row = blockIdx.x;
    long base = row*(long)Nq;
    int t = threadIdx.x;
    float s = 0.f;
#pragma unroll
    for (int l=0;l<4;l++){
        int m = t+l*256;
        float v = fminf(a1[base+m]+a2[base+m], 1.f);
        adjo[base+m]=v; s+=v;
    }
    __shared__ float sm[8];
    s = warp_red_sum(s);
    if ((t&31)==0) sm[t>>5]=s;
    __syncthreads();
    if (t==0){
        float tot=0.f;
#pragma unroll
        for (int w=0;w<8;w++) tot+=sm[w];
        den[row]=tot+1e-7f;
    }
}

__global__ void init_k(const float* __restrict__ text, float* __restrict__ o1, float* __restrict__ o2){
    for (long i = blockIdx.x*256L + threadIdx.x; i < (long)BNr*Hq; i += (long)gridDim.x*256)
    { float v=text[i]; o1[i]=v; o2[i]=v; }
}

// ---------------- host-side GEMM launcher ----------------
template<int AM,int BM,int EPI>
static void G(const float*A,const float*Bm,float*C,int M,int Nc,int Kd,
              int lda,int ldb,int ldc,long sa,long sb,long sc,int batch,
              const float*bias,const float*res,const float*st1,const float*st2,
              const float*tmv,float scale){
    dim3 grid((Nc+63)/64,(M+63)/64,batch);
    gemm_k<AM,BM,EPI><<<grid,256>>>(A,Bm,C,M,Nc,Kd,lda,ldb,ldc,sa,sb,sc,bias,res,st1,st2,tmv,scale);
}

extern "C" void kernel_launch(void* const* d_in, const int* in_sizes, int n_in,
                              void* d_out, int out_size)
{
    const float* text  = (const float*)d_in[0];
    const float* adj1  = (const float*)d_in[1];
    const float* adj2  = (const float*)d_in[2];
    const float* tmask = (const float*)d_in[5];
    const float* gcn_w = (const float*)d_in[6];
    const float* mut_w = (const float*)d_in[7];
    const float* qw=(const float*)d_in[8],  *qb=(const float*)d_in[9];
    const float* kw=(const float*)d_in[10], *kb=(const float*)d_in[11];
    const float* vw=(const float*)d_in[12], *vb=(const float*)d_in[13];
    const float* aw=(const float*)d_in[14], *ab=(const float*)d_in[15];
    const float* g1=(const float*)d_in[16], *b1=(const float*)d_in[17];
    const float* iw=(const float*)d_in[18], *ib=(const float*)d_in[19];
    const float* ow=(const float*)d_in[20], *ob=(const float*)d_in[21];
    const float* g2=(const float*)d_in[22], *b2=(const float*)d_in[23];

    float* out  = (float*)d_out;
    float* adjo = out + (long)BNr*Hq;     // adj output region

    void* p;
    cudaGetSymbolAddress(&p, g_outs);   float* outs=(float*)p;
    cudaGetSymbolAddress(&p, g_output); float* outp=(float*)p;
    cudaGetSymbolAddress(&p, g_bufA);   float* bA=(float*)p;
    cudaGetSymbolAddress(&p, g_bufB);   float* bB=(float*)p;
    cudaGetSymbolAddress(&p, g_bufC);   float* bC=(float*)p;
    cudaGetSymbolAddress(&p, g_scores); float* sc=(float*)p;
    cudaGetSymbolAddress(&p, g_denom);  float* den=(float*)p;
    cudaGetSymbolAddress(&p, g_rmax);   float* rmax=(float*)p;
    cudaGetSymbolAddress(&p, g_rsum);   float* rsum=(float*)p;
    cudaGetSymbolAddress(&p, g_cmax);   float* cmax=(float*)p;
    cudaGetSymbolAddress(&p, g_csum);   float* csum=(float*)p;
    cudaGetSymbolAddress(&p, g_pmax);   float* pmax=(float*)p;
    cudaGetSymbolAddress(&p, g_psum);   float* psum=(float*)p;

    const long sNH = (long)Nq*Hq;
    const long sNN = (long)Nq*Nq;
    const float rscale = 1.0f/sqrtf((float)Hq);

    init_k<<<640,256>>>(text, outs, outp);
    adj_k<<<BNr,256>>>(adj1, adj2, adjo, den);

    for (int i=0;i<3;i++){
        const float *qwi=qw+i*Hq*Hq, *qbi=qb+i*Hq;
        const float *kwi=kw+i*Hq*Hq, *kbi=kb+i*Hq;
        const float *vwi=vw+i*Hq*Hq, *vbi=vb+i*Hq;
        const float *awi=aw+i*Hq*Hq, *abi=ab+i*Hq;
        const float *iwi=iw+i*Hq*Hq, *ibi=ib+i*Hq;
        const float *owi=ow+i*Hq*Hq, *obi=ob+i*Hq;
        const float *g1i=g1+i*Hq, *b1i=b1+i*Hq, *g2i=g2+i*Hq, *b2i=b2+i*Hq;

        // ---- BERT layer ----
        G<0,0,0>(outs,qwi,bA, BNr,Hq,Hq, Hq,Hq,Hq, 0,0,0, 1, qbi,0,0,0,0,0.f);     // q
        G<0,0,0>(outs,kwi,bB, BNr,Hq,Hq, Hq,Hq,Hq, 0,0,0, 1, kbi,0,0,0,0,0.f);     // k
        G<0,0,0>(outs,vwi,bC, BNr,Hq,Hq, Hq,Hq,Hq, 0,0,0, 1, vbi,0,0,0,0,0.f);     // v
        G<0,1,3>(bA,bB,sc, Nq,Nq,Hq, Hq,Hq,Nq, sNH,sNH,sNN, Bq, 0,0,0,0, tmask, rscale); // scores + keymask
        softmax_row_k<true><<<BNr,256>>>(sc, 0, 0);
        G<0,0,0>(sc,bC,bA, Nq,Hq,Nq, Nq,Hq,Hq, sNN,sNH,sNH, Bq, 0,0,0,0,0,0.f);    // ctx
        G<0,0,1>(bA,awi,bB, BNr,Hq,Hq, Hq,Hq,Hq, 0,0,0, 1, abi, outs, 0,0,0,0.f);  // pre-LN1
        ln_k<<<BNr,32>>>(bB, g1i, b1i, bC);                                         // attn
        G<0,0,2>(bC,iwi,bA, BNr,Hq,Hq, Hq,Hq,Hq, 0,0,0, 1, ibi,0,0,0,0,0.f);       // inter (gelu)
        G<0,0,1>(bA,owi,bB, BNr,Hq,Hq, Hq,Hq,Hq, 0,0,0, 1, obi, bC, 0,0,0,0.f);    // pre-LN2
        ln_k<<<BNr,32>>>(bB, g2i, b2i, outs);                                       // outs updated

        // ---- GCN propagation ----
        G<0,0,0>(outp,gcn_w,bA, BNr,Hq,Hq, Hq,Hq,Hq, 0,0,0, 1, 0,0,0,0,0,0.f);     // teout
        G<0,0,5>(adjo,bA,bB, Nq,Hq,Nq, Nq,Hq,Hq, sNN,sNH,sNH, Bq, 0, outp, den, 0, 0, 0.f);
        { float* t_=outp; outp=bB; bB=t_; }                                         // output <- new

        // ---- self-alignment ----
        G<0,0,0>(outs,mut_w,bA, BNr,Hq,Hq, Hq,Hq,Hq, 0,0,0, 1, 0,0,0,0,0,0.f);     // mo
        G<0,1,4>(bA,outp,sc, Nq,Nq,Hq, Hq,Hq,Nq, sNH,sNH,sNN, Bq, 0,0,0,0, tmask, 0.f); // logit + pairmask
        softmax_row_k<false><<<BNr,256>>>(sc, rmax, rsum);
        colstats_part<<<dim3(BNr/256,NCH),256>>>(sc, pmax, psum);
        colstats_comb<<<BNr/256,256>>>(pmax, psum, cmax, csum);
        G<1,0,6>(sc,outp,bC, Nq,Hq,Nq, Nq,Hq,Hq, sNN,sNH,sNH, Bq, 0, outs, rmax, rsum, tmask, 0.f); // new_outs
        G<2,0,6>(sc,outs,bB, Nq,Hq,Nq, Nq,Hq,Hq, sNN,sNH,sNH, Bq, 0, outp, cmax, csum, tmask, 0.f); // new_output
        { float* t_=outs; outs=bC; bC=t_; }
        { float* t_=outp; outp=bB; bB=t_; }
    }

    cudaMemcpyAsync(out, outs, (size_t)BNr*Hq*sizeof(float), cudaMemcpyDeviceToDevice);
}

// round 5
// speedup vs baseline: 1.0054x; 1.0054x over previous
#include <cuda_runtime.h>
#include <math.h>

#define Bq   8
#define Nq   1024
#define Hq   200
#define BNr  (Bq*Nq)
#define NCH  8

// ---------------- scratch (no allocs allowed) ----------------
__device__ float g_outs  [BNr*Hq];
__device__ float g_output[BNr*Hq];
__device__ float g_bufA  [BNr*Hq];
__device__ float g_bufB  [BNr*Hq];
__device__ float g_bufC  [BNr*Hq];
__device__ float g_scores[Bq*Nq*Nq];
__device__ float g_denom [BNr];
__device__ float g_rmax  [BNr];
__device__ float g_rsum  [BNr];
__device__ float g_cmax  [BNr];
__device__ float g_csum  [BNr];
__device__ float g_pmax  [NCH*BNr];
__device__ float g_psum  [NCH*BNr];

// ---------------- helpers ----------------
__device__ __forceinline__ float warp_red_sum(float v){
#pragma unroll
    for (int o=16;o;o>>=1) v += __shfl_xor_sync(0xffffffffu, v, o);
    return v;
}
__device__ __forceinline__ float warp_red_max(float v){
#pragma unroll
    for (int o=16;o;o>>=1) v = fmaxf(v, __shfl_xor_sync(0xffffffffu, v, o));
    return v;
}

// ---------------- unified tiled GEMM ----------------
// C[b,i,j] = epi( sum_k Aelem(b,i,k) * Belem(b,k,j) )
// AM: 0 plain row-major A[b,i,k]; 1 expf(A[b,i,k]-stat1[b*M+i]); 2 expf(A[b,k,i]-stat1[b*M+i]) (transposed)
// BM: 0 row-major B[b,k,j]; 1 transposed B[b,j,k]
// EPI: 0 +bias(opt); 1 +bias+res; 2 gelu(+bias); 3 *scale+keymask; 4 +pairmask;
//      5 relu(acc/stat1[b,i])+res; 6 acc/stat2[b,i]*tm[b,i]+res
template<int AM,int BM,int EPI>
__global__ void __launch_bounds__(256)
gemm_k(const float* __restrict__ A, const float* __restrict__ Bm, float* __restrict__ C,
       int M, int Nc, int Kd, int lda, int ldb, int ldc,
       long sA_, long sB_, long sC_,
       const float* __restrict__ bias, const float* __restrict__ res,
       const float* __restrict__ st1,  const float* __restrict__ st2,
       const float* __restrict__ tm, float scale)
{
    __shared__ float shA[64][17];
    __shared__ float shB[16][65];
    const int b  = blockIdx.z;
    const int i0 = blockIdx.y*64, j0 = blockIdx.x*64;
    const int tid = threadIdx.x;
    const int tx = tid & 15, ty = tid >> 4;
    const float* Ab = A + (long)b*sA_;
    const float* Bb = Bm + (long)b*sB_;

    float acc[4][4];
#pragma unroll
    for (int ii=0;ii<4;ii++)
#pragma unroll
        for (int jj=0;jj<4;jj++) acc[ii][jj]=0.f;

    for (int k0=0;k0<Kd;k0+=16){
        // ---- load A tile 64x16 ----
        if (AM==2){
#pragma unroll
            for (int l=0;l<4;l++){
                int idx=l*256+tid; int kk=idx>>6, row=idx&63;
                int gi=i0+row, gk=k0+kk;
                float v=0.f;
                if (gi<M && gk<Kd) v = __expf(Ab[(long)gk*lda+gi] - st1[b*M+gi]);
                shA[row][kk]=v;
            }
        } else {
#pragma unroll
            for (int l=0;l<4;l++){
                int idx=l*256+tid; int row=idx>>4, kk=idx&15;
                int gi=i0+row, gk=k0+kk;
                float v=0.f;
                if (gi<M && gk<Kd){
                    v = Ab[(long)gi*lda+gk];
                    if (AM==1) v = __expf(v - st1[b*M+gi]);
                }
                shA[row][kk]=v;
            }
        }
        // ---- load B tile 16x64 ----
        if (BM==0){
#pragma unroll
            for (int l=0;l<4;l++){
                int idx=l*256+tid; int kk=idx>>6, col=idx&63;
                int gk=k0+kk, gj=j0+col;
                shB[kk][col] = (gk<Kd && gj<Nc) ? Bb[(long)gk*ldb+gj] : 0.f;
            }
        } else {
#pragma unroll
            for (int l=0;l<4;l++){
                int idx=l*256+tid; int col=idx>>4, kk=idx&15;
                int gk=k0+kk, gj=j0+col;
                shB[kk][col] = (gk<Kd && gj<Nc) ? Bb[(long)gj*ldb+gk] : 0.f;
            }
        }
        __syncthreads();
#pragma unroll
        for (int kk=0;kk<16;kk++){
            float a[4], bb[4];
#pragma unroll
            for (int ii=0;ii<4;ii++) a[ii]=shA[ty*4+ii][kk];
#pragma unroll
            for (int jj=0;jj<4;jj++) bb[jj]=shB[kk][tx*4+jj];
#pragma unroll
            for (int ii=0;ii<4;ii++)
#pragma unroll
                for (int jj=0;jj<4;jj++)
                    acc[ii][jj] = fmaf(a[ii], bb[jj], acc[ii][jj]);
        }
        __syncthreads();
    }
    // ---- epilogue ----
#pragma unroll
    for (int ii=0;ii<4;ii++){
        int gi=i0+ty*4+ii;
        if (gi>=M) continue;
#pragma unroll
        for (int jj=0;jj<4;jj++){
            int gj=j0+tx*4+jj;
            if (gj>=Nc) continue;
            float v = acc[ii][jj];
            long cidx = (long)b*sC_ + (long)gi*ldc + gj;
            if (EPI==0){ if (bias) v += bias[gj]; }
            else if (EPI==1){ v += bias[gj]; v += res[cidx]; }
            else if (EPI==2){ v += bias[gj]; v = 0.5f*v*(1.f+erff(v*0.70710678f)); }
            else if (EPI==3){ v = v*scale + (tm[b*Nq+gj]-1.f)*10000.f; }
            else if (EPI==4){ v = v + (tm[b*Nq+gi]*tm[b*Nq+gj]-1.f)*10000.f; }
            else if (EPI==5){ v = fmaxf(v/st1[b*M+gi], 0.f) + res[cidx]; }
            else if (EPI==6){ v = v/st2[b*M+gi]*tm[b*Nq+gi] + res[cidx]; }
            C[cidx] = v;
        }
    }
}

// ---------------- softmax / stats ----------------
template<bool WRITE>
__global__ void __launch_bounds__(256)
softmax_row_k(float* __restrict__ S, float* __restrict__ rmax, float* __restrict__ rsum){
    long row = blockIdx.x;
    float* p = S + row*(long)Nq;
    int t = threadIdx.x;
    float v[4];
    float mx = -1e30f;
#pragma unroll
    for (int l=0;l<4;l++){ v[l]=p[t+l*256]; mx=fmaxf(mx,v[l]); }
    __shared__ float sm[8];
    mx = warp_red_max(mx);
    if ((t&31)==0) sm[t>>5]=mx;
    __syncthreads();
    float m2 = sm[0];
#pragma unroll
    for (int w=1;w<8;w++) m2 = fmaxf(m2, sm[w]);
    float s = 0.f;
#pragma unroll
    for (int l=0;l<4;l++){ v[l]=__expf(v[l]-m2); s+=v[l]; }
    __syncthreads();
    s = warp_red_sum(s);
    if ((t&31)==0) sm[t>>5]=s;
    __syncthreads();
    float st = 0.f;
#pragma unroll
    for (int w=0;w<8;w++) st += sm[w];
    if (WRITE){
        float inv = 1.f/st;
#pragma unroll
        for (int l=0;l<4;l++) p[t+l*256] = v[l]*inv;
    } else if (t==0){ rmax[row]=m2; rsum[row]=st; }
}

__global__ void __launch_bounds__(256)
colstats_part(const float* __restrict__ L, float* __restrict__ pmax, float* __restrict__ psum){
    int g  = blockIdx.x*256 + threadIdx.x;       // 0..BNr-1 : (b,m)
    int ch = blockIdx.y;
    int b = g >> 10, m = g & 1023;
    const float* p = L + (long)b*Nq*Nq + m + (long)ch*(Nq/NCH)*Nq;
    float mx=-1e30f, s=0.f;
#pragma unroll 4
    for (int n=0;n<Nq/NCH;n++){
        float x = p[(long)n*Nq];
        if (x>mx){ s = s*__expf(mx-x) + 1.f; mx = x; }
        else       s += __expf(x-mx);
    }
    pmax[ch*BNr+g]=mx; psum[ch*BNr+g]=s;
}
__global__ void __launch_bounds__(256)
colstats_comb(const float* __restrict__ pmax, const float* __restrict__ psum,
              float* __restrict__ cmax, float* __restrict__ csum){
    int g = blockIdx.x*256 + threadIdx.x;
    float mx=-1e30f, s=0.f;
#pragma unroll
    for (int ch=0; ch<NCH; ch++){
        float m2=pmax[ch*BNr+g], s2=psum[ch*BNr+g];
        if (m2>mx){ s = s*__expf(mx-m2) + s2; mx = m2; }
        else        s += s2*__expf(m2-mx);
    }
    cmax[g]=mx; csum[g]=s;
}

// ---------------- layernorm (1 warp / row, H=200) ----------------
__global__ void __launch_bounds__(32)
ln_k(const float* __restrict__ X, const float* __restrict__ g,
     const float* __restrict__ bt, float* __restrict__ Y){
    long row = blockIdx.x;
    const float* x = X + row*Hq;
    float* y = Y + row*Hq;
    int t = threadIdx.x;
    float v[7]; float s=0.f;
#pragma unroll
    for (int l=0;l<7;l++){ int c=t+l*32; v[l]=(c<Hq)?x[c]:0.f; s+=v[l]; }
    s = warp_red_sum(s);
    float mu = s*(1.f/Hq);
    float var = 0.f;
#pragma unroll
    for (int l=0;l<7;l++){ int c=t+l*32; if (c<Hq){ float d=v[l]-mu; var+=d*d; } }
    var = warp_red_sum(var)*(1.f/Hq);
    float r = rsqrtf(var + 1e-20f);
#pragma unroll
    for (int l=0;l<7;l++){ int c=t+l*32; if (c<Hq) y[c] = (v[l]-mu)*r*g[c]+bt[c]; }
}

// ---------------- adj + denom ----------------
__global__ void __launch_bounds__(256)
adj_k(const float* __restrict__ a1, const float* __restrict__ a2,
      float* __restrict__ adjo, float* __restrict__ den){
    long row = blockIdx.x;
    long base = row*(long)Nq;
    int t = threadIdx.x;
    float s = 0.f;
#pragma unroll
    for (int l=0;l<4;l++){
        int m = t+l*256;
        float v = fminf(a1[base+m]+a2[base+m], 1.f);
        adjo[base+m]=v; s+=v;
    }
    __shared__ float sm[8];
    s = warp_red_sum(s);
    if ((t&31)==0) sm[t>>5]=s;
    __syncthreads();
    if (t==0){
        float tot=0.f;
#pragma unroll
        for (int w=0;w<8;w++) tot+=sm[w];
        den[row]=tot+1e-7f;
    }
}

__global__ void init_k(const float* __restrict__ text, float* __restrict__ o1, float* __restrict__ o2){
    for (long i = blockIdx.x*256L + threadIdx.x; i < (long)BNr*Hq; i += (long)gridDim.x*256)
    { float v=text[i]; o1[i]=v; o2[i]=v; }
}

// ---------------- host-side GEMM launcher ----------------
template<int AM,int BM,int EPI>
static void G(const float*A,const float*Bm,float*C,int M,int Nc,int Kd,
              int lda,int ldb,int ldc,long sa,long sb,long sc,int batch,
              const float*bias,const float*res,const float*st1,const float*st2,
              const float*tmv,float scale){
    dim3 grid((Nc+63)/64,(M+63)/64,batch);
    gemm_k<AM,BM,EPI><<<grid,256>>>(A,Bm,C,M,Nc,Kd,lda,ldb,ldc,sa,sb,sc,bias,res,st1,st2,tmv,scale);
}

extern "C" void kernel_launch(void* const* d_in, const int* in_sizes, int n_in,
                              void* d_out, int out_size)
{
    const float* text  = (const float*)d_in[0];
    const float* adj1  = (const float*)d_in[1];
    const float* adj2  = (const float*)d_in[2];
    const float* tmask = (const float*)d_in[5];
    const float* gcn_w = (const float*)d_in[6];
    const float* mut_w = (const float*)d_in[7];
    const float* qw=(const float*)d_in[8],  *qb=(const float*)d_in[9];
    const float* kw=(const float*)d_in[10], *kb=(const float*)d_in[11];
    const float* vw=(const float*)d_in[12], *vb=(const float*)d_in[13];
    const float* aw=(const float*)d_in[14], *ab=(const float*)d_in[15];
    const float* g1=(const float*)d_in[16], *b1=(const float*)d_in[17];
    const float* iw=(const float*)d_in[18], *ib=(const float*)d_in[19];
    const float* ow=(const float*)d_in[20], *ob=(const float*)d_in[21];
    const float* g2=(const float*)d_in[22], *b2=(const float*)d_in[23];

    float* out  = (float*)d_out;
    float* adjo = out + (long)BNr*Hq;     // adj output region

    void* p;
    cudaGetSymbolAddress(&p, g_outs);   float* outs=(float*)p;
    cudaGetSymbolAddress(&p, g_output); float* outp=(float*)p;
    cudaGetSymbolAddress(&p, g_bufA);   float* bA=(float*)p;
    cudaGetSymbolAddress(&p, g_bufB);   float* bB=(float*)p;
    cudaGetSymbolAddress(&p, g_bufC);   float* bC=(float*)p;
    cudaGetSymbolAddress(&p, g_scores); float* sc=(float*)p;
    cudaGetSymbolAddress(&p, g_denom);  float* den=(float*)p;
    cudaGetSymbolAddress(&p, g_rmax);   float* rmax=(float*)p;
    cudaGetSymbolAddress(&p, g_rsum);   float* rsum=(float*)p;
    cudaGetSymbolAddress(&p, g_cmax);   float* cmax=(float*)p;
    cudaGetSymbolAddress(&p, g_csum);   float* csum=(float*)p;
    cudaGetSymbolAddress(&p, g_pmax);   float* pmax=(float*)p;
    cudaGetSymbolAddress(&p, g_psum);   float* psum=(float*)p;

    const long sNH = (long)Nq*Hq;
    const long sNN = (long)Nq*Nq;
    const float rscale = 1.0f/sqrtf((float)Hq);

    init_k<<<640,256>>>(text, outs, outp);
    adj_k<<<BNr,256>>>(adj1, adj2, adjo, den);

    for (int i=0;i<3;i++){
        const float *qwi=qw+i*Hq*Hq, *qbi=qb+i*Hq;
        const float *kwi=kw+i*Hq*Hq, *kbi=kb+i*Hq;
        const float *vwi=vw+i*Hq*Hq, *vbi=vb+i*Hq;
        const float *awi=aw+i*Hq*Hq, *abi=ab+i*Hq;
        const float *iwi=iw+i*Hq*Hq, *ibi=ib+i*Hq;
        const float *owi=ow+i*Hq*Hq, *obi=ob+i*Hq;
        const float *g1i=g1+i*Hq, *b1i=b1+i*Hq, *g2i=g2+i*Hq, *b2i=b2+i*Hq;

        // ---- BERT layer ----
        G<0,0,0>(outs,qwi,bA, BNr,Hq,Hq, Hq,Hq,Hq, 0,0,0, 1, qbi,0,0,0,0,0.f);     // q
        G<0,0,0>(outs,kwi,bB, BNr,Hq,Hq, Hq,Hq,Hq, 0,0,0, 1, kbi,0,0,0,0,0.f);     // k
        G<0,0,0>(outs,vwi,bC, BNr,Hq,Hq, Hq,Hq,Hq, 0,0,0, 1, vbi,0,0,0,0,0.f);     // v
        G<0,1,3>(bA,bB,sc, Nq,Nq,Hq, Hq,Hq,Nq, sNH,sNH,sNN, Bq, 0,0,0,0, tmask, rscale); // scores + keymask
        softmax_row_k<true><<<BNr,256>>>(sc, 0, 0);
        G<0,0,0>(sc,bC,bA, Nq,Hq,Nq, Nq,Hq,Hq, sNN,sNH,sNH, Bq, 0,0,0,0,0,0.f);    // ctx
        G<0,0,1>(bA,awi,bB, BNr,Hq,Hq, Hq,Hq,Hq, 0,0,0, 1, abi, outs, 0,0,0,0.f);  // pre-LN1
        ln_k<<<BNr,32>>>(bB, g1i, b1i, bC);                                         // attn
        G<0,0,2>(bC,iwi,bA, BNr,Hq,Hq, Hq,Hq,Hq, 0,0,0, 1, ibi,0,0,0,0,0.f);       // inter (gelu)
        G<0,0,1>(bA,owi,bB, BNr,Hq,Hq, Hq,Hq,Hq, 0,0,0, 1, obi, bC, 0,0,0,0.f);    // pre-LN2
        ln_k<<<BNr,32>>>(bB, g2i, b2i, outs);                                       // outs updated

        // ---- GCN propagation ----
        G<0,0,0>(outp,gcn_w,bA, BNr,Hq,Hq, Hq,Hq,Hq, 0,0,0, 1, 0,0,0,0,0,0.f);     // teout
        G<0,0,5>(adjo,bA,bB, Nq,Hq,Nq, Nq,Hq,Hq, sNN,sNH,sNH, Bq, 0, outp, den, 0, 0, 0.f);
        { float* t_=outp; outp=bB; bB=t_; }                                         // output <- new

        // ---- self-alignment ----
        G<0,0,0>(outs,mut_w,bA, BNr,Hq,Hq, Hq,Hq,Hq, 0,0,0, 1, 0,0,0,0,0,0.f);     // mo
        G<0,1,4>(bA,outp,sc, Nq,Nq,Hq, Hq,Hq,Nq, sNH,sNH,sNN, Bq, 0,0,0,0, tmask, 0.f); // logit + pairmask
        softmax_row_k<false><<<BNr,256>>>(sc, rmax, rsum);
        colstats_part<<<dim3(BNr/256,NCH),256>>>(sc, pmax, psum);
        colstats_comb<<<BNr/256,256>>>(pmax, psum, cmax, csum);
        G<1,0,6>(sc,outp,bC, Nq,Hq,Nq, Nq,Hq,Hq, sNN,sNH,sNH, Bq, 0, outs, rmax, rsum, tmask, 0.f); // new_outs
        G<2,0,6>(sc,outs,bB, Nq,Hq,Nq, Nq,Hq,Hq, sNN,sNH,sNH, Bq, 0, outp, cmax, csum, tmask, 0.f); // new_output
        { float* t_=outs; outs=bC; bC=t_; }
        { float* t_=outp; outp=bB; bB=t_; }
    }

    cudaMemcpyAsync(out, outs, (size_t)BNr*Hq*sizeof(float), cudaMemcpyDeviceToDevice);
}

// round 6
// speedup vs baseline: 1.6074x; 1.5987x over previous
#include <cuda_runtime.h>
#include <math.h>

#define Bq   8
#define Nq   1024
#define Hq   200
#define BNr  (Bq*Nq)
#define NCH  8

// ---------------- scratch (no allocs allowed) ----------------
__device__ float g_outs  [BNr*Hq];
__device__ float g_output[BNr*Hq];
__device__ float g_bufA  [BNr*Hq];
__device__ float g_bufB  [BNr*Hq];
__device__ float g_bufC  [BNr*Hq];
__device__ float g_scores[Bq*Nq*Nq];
__device__ float g_denom [BNr];
__device__ float g_rmax  [BNr];
__device__ float g_rsum  [BNr];
__device__ float g_cmax  [BNr];
__device__ float g_csum  [BNr];
__device__ float g_pmax  [NCH*BNr];
__device__ float g_psum  [NCH*BNr];

// ---------------- helpers ----------------
__device__ __forceinline__ float warp_red_sum(float v){
#pragma unroll
    for (int o=16;o;o>>=1) v += __shfl_xor_sync(0xffffffffu, v, o);
    return v;
}
__device__ __forceinline__ float warp_red_max(float v){
#pragma unroll
    for (int o=16;o;o>>=1) v = fmaxf(v, __shfl_xor_sync(0xffffffffu, v, o));
    return v;
}

// packed fp32x2 FMA (FFMA2) — only reachable via explicit PTX
__device__ __forceinline__ unsigned long long pack2(float x){
    unsigned long long r;
    asm("mov.b64 %0, {%1, %1};" : "=l"(r) : "f"(x));
    return r;
}
__device__ __forceinline__ void ffma2(unsigned long long &d,
                                      unsigned long long a,
                                      unsigned long long b){
    asm("fma.rn.f32x2 %0, %1, %2, %0;" : "+l"(d) : "l"(a), "l"(b));
}
__device__ __forceinline__ void unpack2(unsigned long long v, float &lo, float &hi){
    asm("mov.b64 {%0, %1}, %2;" : "=f"(lo), "=f"(hi) : "l"(v));
}

// ---------------- unified tiled GEMM (128x64 tile, 8x4 micro, FFMA2) ----------------
// C[b,i,j] = epi( sum_k Aelem(b,i,k) * Belem(b,k,j) )
// AM: 0 plain row-major A[b,i,k]; 1 expf(A[b,i,k]-st1[b*M+i]); 2 expf(A[b,k,i]-st1[b*M+i]) (transposed)
// BM: 0 row-major B[b,k,j]; 1 transposed B[b,j,k]
// EPI: 0 +bias(opt); 1 +bias+res; 2 gelu(+bias); 3 *scale+keymask; 4 +pairmask;
//      5 relu(acc/st1)+res; 6 acc/st2*tm+res
// Requires: M % 128 == 0 (true for all call sites: M in {8192, 1024})
template<int AM,int BM,int EPI>
__global__ void __launch_bounds__(256,2)
gemm_k(const float* __restrict__ A, const float* __restrict__ Bm, float* __restrict__ C,
       int M, int Nc, int Kd, int lda, int ldb, int ldc,
       long sA_, long sB_, long sC_,
       const float* __restrict__ bias, const float* __restrict__ res,
       const float* __restrict__ st1,  const float* __restrict__ st2,
       const float* __restrict__ tm, float scale)
{
    __shared__ float shA[16][132];   // [kk][row], padded
    __shared__ float shB[16][68];    // [kk][col], padded
    const int b  = blockIdx.z;
    const int i0 = blockIdx.y*128, j0 = blockIdx.x*64;
    const int tid = threadIdx.x;
    const int tx = tid & 15, ty = tid >> 4;
    const int bM = b*M;
    const float* Ab = A + (long)b*sA_;
    const float* Bb = Bm + (long)b*sB_;

    unsigned long long acc[4][4];
#pragma unroll
    for (int p=0;p<4;p++)
#pragma unroll
        for (int j=0;j<4;j++) acc[p][j]=0ull;

    // register staging
    float4 ra4[2];          // AM 0/1
    float  ra [8];          // AM 2
    float  rb [4];

    auto loadA = [&](int k0){
        if (AM==2){
#pragma unroll
            for (int p=0;p<8;p++){
                int idx = p*256+tid; int row = idx&127, kk = idx>>7;
                int gi = i0+row, gk = k0+kk;
                float v = 0.f;
                if (gk<Kd) v = __expf(Ab[(long)gk*lda+gi] - st1[bM+gi]);
                ra[p]=v;
            }
        } else {
            int q = tid&3, r0 = tid>>2;
#pragma unroll
            for (int p=0;p<2;p++){
                int row = p*64 + r0;
                int gi = i0+row, gk = k0 + q*4;
                float4 v = make_float4(0.f,0.f,0.f,0.f);
                if (gk+3 < Kd){
                    v = *(const float4*)&Ab[(long)gi*lda+gk];
                    if (AM==1){
                        float m = st1[bM+gi];
                        v.x=__expf(v.x-m); v.y=__expf(v.y-m);
                        v.z=__expf(v.z-m); v.w=__expf(v.w-m);
                    }
                }
                ra4[p]=v;
            }
        }
    };
    auto storeA = [&](){
        if (AM==2){
#pragma unroll
            for (int p=0;p<8;p++){
                int idx = p*256+tid;
                shA[idx>>7][idx&127] = ra[p];
            }
        } else {
            int q = tid&3, r0 = tid>>2;
#pragma unroll
            for (int p=0;p<2;p++){
                int row = p*64 + r0;
                shA[q*4+0][row]=ra4[p].x;
                shA[q*4+1][row]=ra4[p].y;
                shA[q*4+2][row]=ra4[p].z;
                shA[q*4+3][row]=ra4[p].w;
            }
        }
    };
    auto loadB = [&](int k0){
        if (BM==0){
            int col = tid&63, kb = tid>>6;
#pragma unroll
            for (int p=0;p<4;p++){
                int kk = p*4+kb;
                int gk = k0+kk, gj = j0+col;
                rb[p] = (gk<Kd && gj<Nc) ? Bb[(long)gk*ldb+gj] : 0.f;
            }
        } else {
            int tk = tid&15, cb = tid>>4;
#pragma unroll
            for (int p=0;p<4;p++){
                int col = p*16+cb;
                int gk = k0+tk, gj = j0+col;
                rb[p] = (gk<Kd && gj<Nc) ? Bb[(long)gj*ldb+gk] : 0.f;
            }
        }
    };
    auto storeB = [&](){
        if (BM==0){
            int col = tid&63, kb = tid>>6;
#pragma unroll
            for (int p=0;p<4;p++) shB[p*4+kb][col] = rb[p];
        } else {
            int tk = tid&15, cb = tid>>4;
#pragma unroll
            for (int p=0;p<4;p++) shB[tk][p*16+cb] = rb[p];
        }
    };

    loadA(0); loadB(0);
    int k0 = 0;
    while (true){
        storeA(); storeB();
        __syncthreads();
        int kn = k0+16;
        bool more = kn < Kd;
        if (more){ loadA(kn); loadB(kn); }
#pragma unroll
        for (int kk=0;kk<16;kk++){
            ulonglong2 A0 = *(const ulonglong2*)&shA[kk][ty*8];
            ulonglong2 A1 = *(const ulonglong2*)&shA[kk][ty*8+4];
            float4 bv = *(const float4*)&shB[kk][tx*4];
            unsigned long long b0=pack2(bv.x), b1=pack2(bv.y),
                               b2=pack2(bv.z), b3=pack2(bv.w);
            ffma2(acc[0][0],A0.x,b0); ffma2(acc[0][1],A0.x,b1);
            ffma2(acc[0][2],A0.x,b2); ffma2(acc[0][3],A0.x,b3);
            ffma2(acc[1][0],A0.y,b0); ffma2(acc[1][1],A0.y,b1);
            ffma2(acc[1][2],A0.y,b2); ffma2(acc[1][3],A0.y,b3);
            ffma2(acc[2][0],A1.x,b0); ffma2(acc[2][1],A1.x,b1);
            ffma2(acc[2][2],A1.x,b2); ffma2(acc[2][3],A1.x,b3);
            ffma2(acc[3][0],A1.y,b0); ffma2(acc[3][1],A1.y,b1);
            ffma2(acc[3][2],A1.y,b2); ffma2(acc[3][3],A1.y,b3);
        }
        if (!more) break;
        __syncthreads();
        k0 = kn;
    }

    // ---- epilogue ----
#pragma unroll
    for (int p=0;p<4;p++){
        int gi0 = i0 + ty*8 + p*2;   // rows gi0, gi0+1
#pragma unroll
        for (int j=0;j<4;j++){
            int gj = j0 + tx*4 + j;
            if (gj>=Nc) continue;
            float v0, v1;
            unpack2(acc[p][j], v0, v1);
#pragma unroll
            for (int h=0; h<2; h++){
                int gi = gi0 + h;
                float v = h ? v1 : v0;
                long cidx = (long)b*sC_ + (long)gi*ldc + gj;
                if (EPI==0){ if (bias) v += bias[gj]; }
                else if (EPI==1){ v += bias[gj]; v += res[cidx]; }
                else if (EPI==2){ v += bias[gj]; v = 0.5f*v*(1.f+erff(v*0.70710678f)); }
                else if (EPI==3){ v = v*scale + (tm[b*Nq+gj]-1.f)*10000.f; }
                else if (EPI==4){ v = v + (tm[b*Nq+gi]*tm[b*Nq+gj]-1.f)*10000.f; }
                else if (EPI==5){ v = fmaxf(v/st1[bM+gi], 0.f) + res[cidx]; }
                else if (EPI==6){ v = v/st2[bM+gi]*tm[b*Nq+gi] + res[cidx]; }
                C[cidx] = v;
            }
        }
    }
}

// ---------------- softmax / stats ----------------
template<bool WRITE>
__global__ void __launch_bounds__(256)
softmax_row_k(float* __restrict__ S, float* __restrict__ rmax, float* __restrict__ rsum){
    long row = blockIdx.x;
    float* p = S + row*(long)Nq;
    int t = threadIdx.x;
    float v[4];
    float mx = -1e30f;
#pragma unroll
    for (int l=0;l<4;l++){ v[l]=p[t+l*256]; mx=fmaxf(mx,v[l]); }
    __shared__ float sm[8];
    mx = warp_red_max(mx);
    if ((t&31)==0) sm[t>>5]=mx;
    __syncthreads();
    float m2 = sm[0];
#pragma unroll
    for (int w=1;w<8;w++) m2 = fmaxf(m2, sm[w]);
    float s = 0.f;
#pragma unroll
    for (int l=0;l<4;l++){ v[l]=__expf(v[l]-m2); s+=v[l]; }
    __syncthreads();
    s = warp_red_sum(s);
    if ((t&31)==0) sm[t>>5]=s;
    __syncthreads();
    float st = 0.f;
#pragma unroll
    for (int w=0;w<8;w++) st += sm[w];
    if (WRITE){
        float inv = 1.f/st;
#pragma unroll
        for (int l=0;l<4;l++) p[t+l*256] = v[l]*inv;
    } else if (t==0){ rmax[row]=m2; rsum[row]=st; }
}

__global__ void __launch_bounds__(256)
colstats_part(const float* __restrict__ L, float* __restrict__ pmax, float* __restrict__ psum){
    int g  = blockIdx.x*256 + threadIdx.x;       // 0..BNr-1 : (b,m)
    int ch = blockIdx.y;
    int b = g >> 10, m = g & 1023;
    const float* p = L + (long)b*Nq*Nq + m + (long)ch*(Nq/NCH)*Nq;
    float mx=-1e30f, s=0.f;
#pragma unroll 4
    for (int n=0;n<Nq/NCH;n++){
        float x = p[(long)n*Nq];
        if (x>mx){ s = s*__expf(mx-x) + 1.f; mx = x; }
        else       s += __expf(x-mx);
    }
    pmax[ch*BNr+g]=mx; psum[ch*BNr+g]=s;
}
__global__ void __launch_bounds__(256)
colstats_comb(const float* __restrict__ pmax, const float* __restrict__ psum,
              float* __restrict__ cmax, float* __restrict__ csum){
    int g = blockIdx.x*256 + threadIdx.x;
    float mx=-1e30f, s=0.f;
#pragma unroll
    for (int ch=0; ch<NCH; ch++){
        float m2=pmax[ch*BNr+g], s2=psum[ch*BNr+g];
        if (m2>mx){ s = s*__expf(mx-m2) + s2; mx = m2; }
        else        s += s2*__expf(m2-mx);
    }
    cmax[g]=mx; csum[g]=s;
}

// ---------------- layernorm (1 warp / row, H=200) ----------------
__global__ void __launch_bounds__(32)
ln_k(const float* __restrict__ X, const float* __restrict__ g,
     const float* __restrict__ bt, float* __restrict__ Y){
    long row = blockIdx.x;
    const float* x = X + row*Hq;
    float* y = Y + row*Hq;
    int t = threadIdx.x;
    float v[7]; float s=0.f;
#pragma unroll
    for (int l=0;l<7;l++){ int c=t+l*32; v[l]=(c<Hq)?x[c]:0.f; s+=v[l]; }
    s = warp_red_sum(s);
    float mu = s*(1.f/Hq);
    float var = 0.f;
#pragma unroll
    for (int l=0;l<7;l++){ int c=t+l*32; if (c<Hq){ float d=v[l]-mu; var+=d*d; } }
    var = warp_red_sum(var)*(1.f/Hq);
    float r = rsqrtf(var + 1e-20f);
#pragma unroll
    for (int l=0;l<7;l++){ int c=t+l*32; if (c<Hq) y[c] = (v[l]-mu)*r*g[c]+bt[c]; }
}

// ---------------- adj + denom ----------------
__global__ void __launch_bounds__(256)
adj_k(const float* __restrict__ a1, const float* __restrict__ a2,
      float* __restrict__ adjo, float* __restrict__ den){
    long row = blockIdx.x;
    long base = row*(long)Nq;
    int t = threadIdx.x;
    float s = 0.f;
#pragma unroll
    for (int l=0;l<4;l++){
        int m = t+l*256;
        float v = fminf(a1[base+m]+a2[base+m], 1.f);
        adjo[base+m]=v; s+=v;
    }
    __shared__ float sm[8];
    s = warp_red_sum(s);
    if ((t&31)==0) sm[t>>5]=s;
    __syncthreads();
    if (t==0){
        float tot=0.f;
#pragma unroll
        for (int w=0;w<8;w++) tot+=sm[w];
        den[row]=tot+1e-7f;
    }
}

__global__ void init_k(const float* __restrict__ text, float* __restrict__ o1, float* __restrict__ o2){
    for (long i = blockIdx.x*256L + threadIdx.x; i < (long)BNr*Hq; i += (long)gridDim.x*256)
    { float v=text[i]; o1[i]=v; o2[i]=v; }
}

// ---------------- host-side GEMM launcher ----------------
template<int AM,int BM,int EPI>
static void G(const float*A,const float*Bm,float*C,int M,int Nc,int Kd,
              int lda,int ldb,int ldc,long sa,long sb,long sc,int batch,
              const float*bias,const float*res,const float*st1,const float*st2,
              const float*tmv,float scale){
    dim3 grid((Nc+63)/64, M/128, batch);
    gemm_k<AM,BM,EPI><<<grid,256>>>(A,Bm,C,M,Nc,Kd,lda,ldb,ldc,sa,sb,sc,bias,res,st1,st2,tmv,scale);
}

extern "C" void kernel_launch(void* const* d_in, const int* in_sizes, int n_in,
                              void* d_out, int out_size)
{
    const float* text  = (const float*)d_in[0];
    const float* adj1  = (const float*)d_in[1];
    const float* adj2  = (const float*)d_in[2];
    const float* tmask = (const float*)d_in[5];
    const float* gcn_w = (const float*)d_in[6];
    const float* mut_w = (const float*)d_in[7];
    const float* qw=(const float*)d_in[8],  *qb=(const float*)d_in[9];
    const float* kw=(const float*)d_in[10], *kb=(const float*)d_in[11];
    const float* vw=(const float*)d_in[12], *vb=(const float*)d_in[13];
    const float* aw=(const float*)d_in[14], *ab=(const float*)d_in[15];
    const float* g1=(const float*)d_in[16], *b1=(const float*)d_in[17];
    const float* iw=(const float*)d_in[18], *ib=(const float*)d_in[19];
    const float* ow=(const float*)d_in[20], *ob=(const float*)d_in[21];
    const float* g2=(const float*)d_in[22], *b2=(const float*)d_in[23];

    float* out  = (float*)d_out;
    float* adjo = out + (long)BNr*Hq;     // adj output region

    void* p;
    cudaGetSymbolAddress(&p, g_outs);   float* outs=(float*)p;
    cudaGetSymbolAddress(&p, g_output); float* outp=(float*)p;
    cudaGetSymbolAddress(&p, g_bufA);   float* bA=(float*)p;
    cudaGetSymbolAddress(&p, g_bufB);   float* bB=(float*)p;
    cudaGetSymbolAddress(&p, g_bufC);   float* bC=(float*)p;
    cudaGetSymbolAddress(&p, g_scores); float* sc=(float*)p;
    cudaGetSymbolAddress(&p, g_denom);  float* den=(float*)p;
    cudaGetSymbolAddress(&p, g_rmax);   float* rmax=(float*)p;
    cudaGetSymbolAddress(&p, g_rsum);   float* rsum=(float*)p;
    cudaGetSymbolAddress(&p, g_cmax);   float* cmax=(float*)p;
    cudaGetSymbolAddress(&p, g_csum);   float* csum=(float*)p;
    cudaGetSymbolAddress(&p, g_pmax);   float* pmax=(float*)p;
    cudaGetSymbolAddress(&p, g_psum);   float* psum=(float*)p;

    const long sNH = (long)Nq*Hq;
    const long sNN = (long)Nq*Nq;
    const float rscale = 1.0f/sqrtf((float)Hq);

    init_k<<<640,256>>>(text, outs, outp);
    adj_k<<<BNr,256>>>(adj1, adj2, adjo, den);

    for (int i=0;i<3;i++){
        const float *qwi=qw+i*Hq*Hq, *qbi=qb+i*Hq;
        const float *kwi=kw+i*Hq*Hq, *kbi=kb+i*Hq;
        const float *vwi=vw+i*Hq*Hq, *vbi=vb+i*Hq;
        const float *awi=aw+i*Hq*Hq, *abi=ab+i*Hq;
        const float *iwi=iw+i*Hq*Hq, *ibi=ib+i*Hq;
        const float *owi=ow+i*Hq*Hq, *obi=ob+i*Hq;
        const float *g1i=g1+i*Hq, *b1i=b1+i*Hq, *g2i=g2+i*Hq, *b2i=b2+i*Hq;

        // ---- BERT layer ----
        G<0,0,0>(outs,qwi,bA, BNr,Hq,Hq, Hq,Hq,Hq, 0,0,0, 1, qbi,0,0,0,0,0.f);     // q
        G<0,0,0>(outs,kwi,bB, BNr,Hq,Hq, Hq,Hq,Hq, 0,0,0, 1, kbi,0,0,0,0,0.f);     // k
        G<0,0,0>(outs,vwi,bC, BNr,Hq,Hq, Hq,Hq,Hq, 0,0,0, 1, vbi,0,0,0,0,0.f);     // v
        G<0,1,3>(bA,bB,sc, Nq,Nq,Hq, Hq,Hq,Nq, sNH,sNH,sNN, Bq, 0,0,0,0, tmask, rscale); // scores + keymask
        softmax_row_k<true><<<BNr,256>>>(sc, 0, 0);
        G<0,0,0>(sc,bC,bA, Nq,Hq,Nq, Nq,Hq,Hq, sNN,sNH,sNH, Bq, 0,0,0,0,0,0.f);    // ctx
        G<0,0,1>(bA,awi,bB, BNr,Hq,Hq, Hq,Hq,Hq, 0,0,0, 1, abi, outs, 0,0,0,0.f);  // pre-LN1
        ln_k<<<BNr,32>>>(bB, g1i, b1i, bC);                                         // attn
        G<0,0,2>(bC,iwi,bA, BNr,Hq,Hq, Hq,Hq,Hq, 0,0,0, 1, ibi,0,0,0,0,0.f);       // inter (gelu)
        G<0,0,1>(bA,owi,bB, BNr,Hq,Hq, Hq,Hq,Hq, 0,0,0, 1, obi, bC, 0,0,0,0.f);    // pre-LN2
        ln_k<<<BNr,32>>>(bB, g2i, b2i, outs);                                       // outs updated

        // ---- GCN propagation ----
        G<0,0,0>(outp,gcn_w,bA, BNr,Hq,Hq, Hq,Hq,Hq, 0,0,0, 1, 0,0,0,0,0,0.f);     // teout
        G<0,0,5>(adjo,bA,bB, Nq,Hq,Nq, Nq,Hq,Hq, sNN,sNH,sNH, Bq, 0, outp, den, 0, 0, 0.f);
        { float* t_=outp; outp=bB; bB=t_; }                                         // output <- new

        // ---- self-alignment ----
        G<0,0,0>(outs,mut_w,bA, BNr,Hq,Hq, Hq,Hq,Hq, 0,0,0, 1, 0,0,0,0,0,0.f);     // mo
        G<0,1,4>(bA,outp,sc, Nq,Nq,Hq, Hq,Hq,Nq, sNH,sNH,sNN, Bq, 0,0,0,0, tmask, 0.f); // logit + pairmask
        softmax_row_k<false><<<BNr,256>>>(sc, rmax, rsum);
        colstats_part<<<dim3(BNr/256,NCH),256>>>(sc, pmax, psum);
        colstats_comb<<<BNr/256,256>>>(pmax, psum, cmax, csum);
        G<1,0,6>(sc,outp,bC, Nq,Hq,Nq, Nq,Hq,Hq, sNN,sNH,sNH, Bq, 0, outs, rmax, rsum, tmask, 0.f); // new_outs
        G<2,0,6>(sc,outs,bB, Nq,Hq,Nq, Nq,Hq,Hq, sNN,sNH,sNH, Bq, 0, outp, cmax, csum, tmask, 0.f); // new_output
        { float* t_=outs; outs=bC; bC=t_; }
        { float* t_=outp; outp=bB; bB=t_; }
    }

    cudaMemcpyAsync(out, outs, (size_t)BNr*Hq*sizeof(float), cudaMemcpyDeviceToDevice);
}